// round 12
// baseline (speedup 1.0000x reference)
#include <cuda_runtime.h>
#include <math.h>

#define NBOX  4096
#define STUP  128                // setup threads; scan runs on warp 0 only
#define SLOTS 3072               // per-class capacity (class ~2048)
#define GC    8                  // 8x8 grid, 128px cells
#define NCELL (GC * GC)
#define FULL  0xFFFFFFFFu

typedef unsigned long long u64;
typedef unsigned u32;

__device__ u64 g_emit[2][NBOX];  // per-class emission keys, descending
__device__ int g_mcnt[2];

struct ScanSmem {
    float4 sbx[SLOTS];           // 48 KB  box per slot (cell-grouped)
    u64    skey[SLOTS];          // 24 KB  (scorebits<<32)|~orig ; 0 = dead
    int    cellof[SLOTS];        // 12 KB  slot -> cell
    u64    cmax[NCELL];          // per-cell max key
    int    cargp[NCELL];         // per-cell argmax slot
    int    cflag[NCELL];         // 1 = cmax stale
    int    cstart[NCELL + 1];
    int    ccnt[NCELL];
    int    ccur[NCELL];
};

extern __shared__ char smem_raw[];

// Recompute max key (+slot) of cell c. Single-warp collective.
__device__ __forceinline__ void cell_reduce(ScanSmem* sm, int c, int lid)
{
    int lo = sm->cstart[c], hi = sm->cstart[c + 1];
    u64 bk = 0ULL; int bp = 0;
    for (int p = lo + lid; p < hi; p += 32) {
        u64 k = sm->skey[p];
        if (k > bk) { bk = k; bp = p; }
    }
    u32 h  = (u32)(bk >> 32);
    u32 wm = __reduce_max_sync(FULL, h);
    u32 l  = (h == wm) ? (u32)bk : 0u;
    u32 wl = __reduce_max_sync(FULL, l);
    u64 win = ((u64)wm << 32) | wl;
    u32 cand = (win != 0ULL && bk == win) ? (u32)(bp + 1) : 0u;
    int ap = (int)__reduce_max_sync(FULL, cand) - 1;
    if (lid == 0) { sm->cmax[c] = win; sm->cargp[c] = ap; }
}

__global__ __launch_bounds__(STUP, 1)
void scan_kernel(const float* __restrict__ g_boxes,
                 const float* __restrict__ g_scores,
                 const int*   __restrict__ g_labels)
{
    ScanSmem* sm = reinterpret_cast<ScanSmem*>(smem_raw);
    const int cls = blockIdx.x;
    const int tid = threadIdx.x;
    const int wid = tid >> 5;
    const int lid = tid & 31;

    // ============ setup with all 128 threads ============
    for (int c = tid; c < NCELL; c += STUP) {
        sm->ccnt[c] = 0; sm->ccur[c] = 0; sm->cflag[c] = 0;
    }
    __syncthreads();
    for (int j = tid; j < NBOX; j += STUP) {
        if (g_labels[j] == cls) {
            float4 b = reinterpret_cast<const float4*>(g_boxes)[j];
            int cell = ((((int)b.y) >> 7) << 3) | (((int)b.x) >> 7);
            atomicAdd(&sm->ccnt[cell], 1);
        }
    }
    __syncthreads();
    if (tid == 0) {
        int run = 0;
        for (int c = 0; c < NCELL; c++) { sm->cstart[c] = run; run += sm->ccnt[c]; }
        sm->cstart[NCELL] = run;
    }
    __syncthreads();
    for (int j = tid; j < NBOX; j += STUP) {
        if (g_labels[j] == cls) {
            float4 b = reinterpret_cast<const float4*>(g_boxes)[j];
            int cell = ((((int)b.y) >> 7) << 3) | (((int)b.x) >> 7);
            int pos = sm->cstart[cell] + atomicAdd(&sm->ccur[cell], 1);
            sm->sbx[pos]    = b;
            sm->skey[pos]   = ((u64)__float_as_uint(g_scores[j]) << 32) | (u32)~j;
            sm->cellof[pos] = cell;
        }
    }
    __syncthreads();
    for (int c = wid; c < NCELL; c += STUP / 32) cell_reduce(sm, c, lid);
    __syncthreads();

    if (wid != 0) return;        // scan is single-warp: no block barriers after

    const int Ng = sm->cstart[NCELL];
    int m = 0;

    // ============ warp-synchronous main scan ============
    for (int t = 0; t < Ng; t++) {
        // A: global argmax over 64 cell maxes (2 per lane, MLP-batched loads).
        u64 k0 = sm->cmax[lid];
        u64 k1 = sm->cmax[lid + 32];
        int a0 = sm->cargp[lid];
        int a1 = sm->cargp[lid + 32];
        u64 bk; int ap;
        if (k1 > k0) { bk = k1; ap = a1; } else { bk = k0; ap = a0; }
        u32 h  = (u32)(bk >> 32);
        u32 wm = __reduce_max_sync(FULL, h);
        if (wm == 0u) break;                                  // class done
        u32 l  = (h == wm) ? (u32)bk : 0u;
        u32 wl = __reduce_max_sync(FULL, l);
        u64 K  = ((u64)wm << 32) | wl;
        u32 pc = (bk == K) ? (u32)(ap + 1) : 0u;
        int selpos = (int)__reduce_max_sync(FULL, pc) - 1;

        // B: selected box; emit; kill slot; flag its cell.
        float4 sb = sm->sbx[selpos];
        float  a1f = (sb.z - sb.x) * (sb.w - sb.y);
        if (lid == 0) {
            g_emit[cls][m] = K;
            sm->skey[selpos] = 0ULL;
            sm->cflag[sm->cellof[selpos]] = 1;
        }
        m++;

        int cx = ((int)sb.x) >> 7,  cy = ((int)sb.y) >> 7;
        int cxlo = max(cx - 1, 0),  cxhi = min(cx + 1, GC - 1);
        int cylo = max(cy - 1, 0),  cyhi = min(cy + 1, GC - 1);

        // D: decay the 3x3 neighborhood; flag a cell only if its argmax
        //    box was modified (scores only decrease -> cmax else valid).
        for (int ry = cylo; ry <= cyhi; ry++) {
            int lo = sm->cstart[ry * GC + cxlo];
            int hi = sm->cstart[ry * GC + cxhi + 1];
            for (int p = lo + lid; p < hi; p += 32) {
                if (p == selpos) continue;
                u64 k = sm->skey[p];
                if (k == 0ULL) continue;
                float4 b = sm->sbx[p];
                float w  = fminf(sb.z, b.z) - fmaxf(sb.x, b.x);
                float hh = fminf(sb.w, b.w) - fmaxf(sb.y, b.y);
                if (w > 0.0f && hh > 0.0f) {
                    float a2    = (b.z - b.x) * (b.w - b.y);
                    float inter = w * hh;
                    float iou   = inter / ((a1f + a2) - inter + 1e-8f);
                    float d     = expf(-(iou * iou) * 2.0f);  // sigma=0.5
                    float nv    = __uint_as_float((u32)(k >> 32)) * d;
                    sm->skey[p] = (nv >= 0.001f)
                        ? (((u64)__float_as_uint(nv) << 32) | (u32)k) : 0ULL;
                    int c = sm->cellof[p];
                    if (sm->cargp[c] == p) sm->cflag[c] = 1;
                }
            }
        }
        __syncwarp();

        // F: repair ONLY flagged cells (usually 1, occasionally 2-3).
        for (int ry = cylo; ry <= cyhi; ry++) {
            for (int rx = cxlo; rx <= cxhi; rx++) {
                int c = ry * GC + rx;
                if (sm->cflag[c]) {
                    cell_reduce(sm, c, lid);
                    if (lid == 0) sm->cflag[c] = 0;
                }
            }
        }
        __syncwarp();
    }

    if (lid == 0) g_mcnt[cls] = m;
}

// ---------------- merge kernel (1 CTA, smem-staged keys) ----------------
#define MNT 1024
__global__ __launch_bounds__(MNT, 1)
void merge_kernel(const float* __restrict__ g_boxes,
                  float* __restrict__ g_out)
{
    __shared__ u64 sA[NBOX];     // list A at [0,mA), list B at [mA, mA+mB)
    const int tid = threadIdx.x;
    const int mA = g_mcnt[0];
    const int mB = g_mcnt[1];

    for (int i = tid; i < mA; i += MNT) sA[i]      = g_emit[0][i];
    for (int i = tid; i < mB; i += MNT) sA[mA + i] = g_emit[1][i];
    __syncthreads();

    float* outBoxes  = g_out;             // [N,4]
    float* outScores = g_out + 4 * NBOX;  // [N]
    float* outLabels = g_out + 5 * NBOX;  // [N] float; -1 padding

    for (int i = tid; i < mA; i += MNT) {
        u64 key = sA[i];
        int lo = 0, hi = mB;
        while (lo < hi) { int mid = (lo + hi) >> 1;
                          if (sA[mA + mid] > key) lo = mid + 1; else hi = mid; }
        int r = i + lo;
        int o = (int)~(u32)key;
        reinterpret_cast<float4*>(outBoxes)[r] =
            reinterpret_cast<const float4*>(g_boxes)[o];
        outScores[r] = __uint_as_float((u32)(key >> 32));
        outLabels[r] = 0.0f;
    }
    for (int i = tid; i < mB; i += MNT) {
        u64 key = sA[mA + i];
        int lo = 0, hi = mA;
        while (lo < hi) { int mid = (lo + hi) >> 1;
                          if (sA[mid] > key) lo = mid + 1; else hi = mid; }
        int r = i + lo;
        int o = (int)~(u32)key;
        reinterpret_cast<float4*>(outBoxes)[r] =
            reinterpret_cast<const float4*>(g_boxes)[o];
        outScores[r] = __uint_as_float((u32)(key >> 32));
        outLabels[r] = 1.0f;
    }
    for (int r = mA + mB + tid; r < NBOX; r += MNT) {
        reinterpret_cast<float4*>(outBoxes)[r] = make_float4(0.f, 0.f, 0.f, 0.f);
        outScores[r] = 0.0f;
        outLabels[r] = -1.0f;
    }
}

extern "C" void kernel_launch(void* const* d_in, const int* in_sizes, int n_in,
                              void* d_out, int out_size)
{
    const float* boxes  = (const float*)d_in[0];
    const float* scores = (const float*)d_in[1];
    const int*   labels = (const int*)d_in[2];
    float*       out    = (float*)d_out;

    size_t smem = sizeof(ScanSmem);
    cudaFuncSetAttribute(scan_kernel,
                         cudaFuncAttributeMaxDynamicSharedMemorySize, (int)smem);
    scan_kernel<<<2, STUP, smem>>>(boxes, scores, labels);
    merge_kernel<<<1, MNT>>>(boxes, out);
}

// round 14
// speedup vs baseline: 2.3322x; 2.3322x over previous
#include <cuda_runtime.h>
#include <math.h>

#define NBOX 4096
#define NT   256                 // threads per class CTA (8 warps)
#define NW   (NT / 32)
#define EPT  9                   // 9*256 = 2304 register capacity per class
#define NCAND (NW * 4)           // 32 candidates: per-warp top-4
#define MAXB 32
#define FULL 0xFFFFFFFFu

typedef unsigned long long u64;
typedef unsigned u32;

__device__ u64 g_emit[2][NBOX];  // per-class emission keys, descending
__device__ int g_mcnt[2];

struct ScanSmem {
    float4 sbox[NBOX];           // orig-indexed boxes                  64 KB
    float  cscore[NBOX];         // compacted scores                    16 KB
    int    corig[NBOX];          // compacted -> orig index             16 KB
    u64    cand[NCAND];          // published candidate keys
    u32    cflag[NCAND];         // 1 = publication was lane's THIRD element
    int    acc[MAXB];            // accepted orig indices (epoch order)
    int    cnt;
};

extern __shared__ char smem_raw[];

__device__ __forceinline__ u64 packkey(float s, int orig) {
    return ((u64)__float_as_uint(fmaxf(s, 0.0f)) << 32) | (u32)~orig;
}

__global__ __launch_bounds__(NT, 1)
void scan_kernel(const float* __restrict__ g_boxes,
                 const float* __restrict__ g_scores,
                 const int*   __restrict__ g_labels)
{
    ScanSmem* sm = reinterpret_cast<ScanSmem*>(smem_raw);
    const int cls = blockIdx.x;
    const int tid = threadIdx.x;
    const int wid = tid >> 5;
    const int lid = tid & 31;

    // ---- load boxes + compact own class ----
    if (tid == 0) sm->cnt = 0;
    __syncthreads();
    for (int j = tid; j < NBOX; j += NT) {
        float4 b = reinterpret_cast<const float4*>(g_boxes)[j];
        sm->sbox[j] = b;
        if (g_labels[j] == cls) {
            int pos = atomicAdd(&sm->cnt, 1);
            sm->cscore[pos] = g_scores[j];
            sm->corig[pos]  = j;
        }
    }
    __syncthreads();
    const int Ng   = sm->cnt;
    const int rbeg = EPT * NT;   // smem overflow start (rarely populated)

    // ---- register-resident owned slots: ci = tid + k*NT ----
    float sc[EPT], bx[EPT], by[EPT], bz[EPT], bw[EPT], ar[EPT];
    int   org[EPT];
#pragma unroll
    for (int k = 0; k < EPT; k++) {
        int ci = tid + k * NT;
        if (ci < Ng) {
            int o = sm->corig[ci];
            float4 b = sm->sbox[o];
            bx[k] = b.x; by[k] = b.y; bz[k] = b.z; bw[k] = b.w;
            ar[k] = (b.z - b.x) * (b.w - b.y);
            sc[k] = sm->cscore[ci];
            org[k] = o;
        } else { sc[k] = -INFINITY; org[k] = -1; }
    }

    bool changed = true;
    u64  la0 = 0, la1 = 0, la2 = 0;   // cached local top-3 (packed keys)
    int  emitted = 0;

    while (true) {
        // ---- recompute local top-3 if owned set changed ----
        if (changed) {
            u64 a = 0, b = 0, c = 0;
#pragma unroll
            for (int k = 0; k < EPT; k++) {
                u64 v = (sc[k] == -INFINITY) ? 0ULL : packkey(sc[k], org[k]);
                if (v > a)      { c = b; b = a; a = v; }
                else if (v > b) { c = b; b = v; }
                else if (v > c) { c = v; }
            }
            for (int ci = rbeg + tid; ci < Ng; ci += NT) {
                float s = sm->cscore[ci];
                u64 v = (s == -INFINITY) ? 0ULL : packkey(s, sm->corig[ci]);
                if (v > a)      { c = b; b = a; a = v; }
                else if (v > b) { c = b; b = v; }
                else if (v > c) { c = v; }
            }
            la0 = a; la1 = b; la2 = c;
            changed = false;
        }

        // ---- publish per-warp top-4 candidates (lanes offer top-3) ----
        {
            int p = 0;
#pragma unroll
            for (int r = 0; r < 4; r++) {
                u64 contrib = (p == 0) ? la0 : ((p == 1) ? la1 :
                              ((p == 2) ? la2 : 0ULL));
                u32 hi = (u32)(contrib >> 32);
                u32 wm = __reduce_max_sync(FULL, hi);
                u32 lo = (hi == wm) ? (u32)contrib : 0u;
                u32 wl = __reduce_max_sync(FULL, lo);
                u64 win = ((u64)wm << 32) | wl;
                if (win != 0ULL && contrib == win) {   // unique winner lane
                    sm->cand[wid * 4 + r]  = win;
                    sm->cflag[wid * 4 + r] = (p == 2) ? 1u : 0u;
                    p++;
                }
                if (win == 0ULL && lid == 0) sm->cand[wid * 4 + r] = 0ULL;
            }
        }
        __syncthreads();

        // ---- load candidates (one per lane) + compute outside bound ----
        // bound >= every non-candidate box's current key:
        //   * warp's 4th-round winner bounds that warp's unpublished lanes
        //   * a published THIRD element bounds that lane's 4th+ elements
        u64 ck = sm->cand[lid];
        u32 third = sm->cflag[lid];
        u64 bref = (ck != 0ULL && (third || (lid & 3) == 3)) ? ck : 0ULL;
        u32 bh = (u32)(bref >> 32);
        u32 bm = __reduce_max_sync(FULL, bh);
        u32 bl = (bh == bm) ? (u32)bref : 0u;
        u32 bml = __reduce_max_sync(FULL, bl);
        u64 bound = ((u64)bm << 32) | bml;

        int corig = -1; float csc = 0.0f, ca = 0.0f;
        float4 cb = make_float4(0.f, 0.f, 0.f, 0.f);
        if (ck != 0ULL) {
            corig = (int)~(u32)ck;
            csc = __uint_as_float((u32)(ck >> 32));
            cb = sm->sbox[corig];
            ca = (cb.z - cb.x) * (cb.w - cb.y);
        }
        u64 cur = ck;

        // ---- batch accept loop (redundant in every warp, no barriers) ----
        int bcount = 0;
        while (true) {
            u32 hi = (u32)(cur >> 32);
            u32 wm = __reduce_max_sync(FULL, hi);
            if (wm == 0u) break;                        // candidates exhausted
            u32 lo = (hi == wm) ? (u32)cur : 0u;
            u32 wl = __reduce_max_sync(FULL, lo);
            u64 win = ((u64)wm << 32) | wl;
            if (bcount > 0 && win < bound) break;       // exactness boundary
            int so = (int)~wl;
            if (tid == 0) { g_emit[cls][emitted] = win; sm->acc[bcount] = so; }
            emitted++; bcount++;

            float4 ab = sm->sbox[so];                   // broadcast LDS
            float  aa = (ab.z - ab.x) * (ab.w - ab.y);

            if (cur != 0ULL) {                          // update my candidate
                if (corig == so) cur = 0ULL;
                else {
                    float w = fminf(ab.z, cb.z) - fmaxf(ab.x, cb.x);
                    float h = fminf(ab.w, cb.w) - fmaxf(ab.y, cb.y);
                    if (w > 0.0f && h > 0.0f) {
                        float inter = w * h;
                        float iou = inter / ((aa + ca) - inter + 1e-8f);
                        float d   = expf(-(iou * iou) * 2.0f);
                        float nv  = csc * d;
                        if (nv >= 0.001f) {
                            csc = nv;
                            cur = ((u64)__float_as_uint(csc) << 32) | (u32)~corig;
                        } else cur = 0ULL;
                    }
                }
            }
            if (bcount >= MAXB) break;
        }

        if (bcount == 0) break;                         // class done
        __syncthreads();                                // acc[] visible

        // ---- deferred owned decay, in emission order (bit-exact) ----
        for (int b = 0; b < bcount; b++) {
            int so = sm->acc[b];
            float4 ab = sm->sbox[so];
            float  aa = (ab.z - ab.x) * (ab.w - ab.y);
#pragma unroll
            for (int k = 0; k < EPT; k++) {
                float v = sc[k];
                if (v != -INFINITY) {
                    if (org[k] == so) { sc[k] = -INFINITY; changed = true; }
                    else {
                        float w = fminf(ab.z, bz[k]) - fmaxf(ab.x, bx[k]);
                        float h = fminf(ab.w, bw[k]) - fmaxf(ab.y, by[k]);
                        if (w > 0.0f && h > 0.0f) {
                            float inter = w * h;
                            float iou = inter / ((aa + ar[k]) - inter + 1e-8f);
                            float d   = expf(-(iou * iou) * 2.0f);
                            float nv  = v * d;
                            sc[k] = (nv >= 0.001f) ? nv : -INFINITY;
                            changed = true;
                        }
                    }
                }
            }
            for (int ci = rbeg + tid; ci < Ng; ci += NT) {   // overflow (rare)
                float v = sm->cscore[ci];
                if (v != -INFINITY) {
                    int o = sm->corig[ci];
                    if (o == so) { sm->cscore[ci] = -INFINITY; changed = true; }
                    else {
                        float4 b2 = sm->sbox[o];
                        float w = fminf(ab.z, b2.z) - fmaxf(ab.x, b2.x);
                        float h = fminf(ab.w, b2.w) - fmaxf(ab.y, b2.y);
                        if (w > 0.0f && h > 0.0f) {
                            float a2 = (b2.z - b2.x) * (b2.w - b2.y);
                            float inter = w * h;
                            float iou = inter / ((aa + a2) - inter + 1e-8f);
                            float d   = expf(-(iou * iou) * 2.0f);
                            float nv  = v * d;
                            sm->cscore[ci] = (nv >= 0.001f) ? nv : -INFINITY;
                            changed = true;
                        }
                    }
                }
            }
        }
    }

    if (tid == 0) g_mcnt[cls] = emitted;
}

// ---------------- merge kernel (1 CTA, smem-staged keys) ----------------
#define MNT 1024
__global__ __launch_bounds__(MNT, 1)
void merge_kernel(const float* __restrict__ g_boxes,
                  float* __restrict__ g_out)
{
    __shared__ u64 sA[NBOX];     // list A at [0,mA), list B at [mA, mA+mB)
    const int tid = threadIdx.x;
    const int mA = g_mcnt[0];
    const int mB = g_mcnt[1];

    for (int i = tid; i < mA; i += MNT) sA[i]      = g_emit[0][i];
    for (int i = tid; i < mB; i += MNT) sA[mA + i] = g_emit[1][i];
    __syncthreads();

    float* outBoxes  = g_out;             // [N,4]
    float* outScores = g_out + 4 * NBOX;  // [N]
    float* outLabels = g_out + 5 * NBOX;  // [N] float; -1 padding

    for (int i = tid; i < mA; i += MNT) {
        u64 key = sA[i];
        int lo = 0, hi = mB;
        while (lo < hi) { int mid = (lo + hi) >> 1;
                          if (sA[mA + mid] > key) lo = mid + 1; else hi = mid; }
        int r = i + lo;
        int o = (int)~(u32)key;
        reinterpret_cast<float4*>(outBoxes)[r] =
            reinterpret_cast<const float4*>(g_boxes)[o];
        outScores[r] = __uint_as_float((u32)(key >> 32));
        outLabels[r] = 0.0f;
    }
    for (int i = tid; i < mB; i += MNT) {
        u64 key = sA[mA + i];
        int lo = 0, hi = mA;
        while (lo < hi) { int mid = (lo + hi) >> 1;
                          if (sA[mid] > key) lo = mid + 1; else hi = mid; }
        int r = i + lo;
        int o = (int)~(u32)key;
        reinterpret_cast<float4*>(outBoxes)[r] =
            reinterpret_cast<const float4*>(g_boxes)[o];
        outScores[r] = __uint_as_float((u32)(key >> 32));
        outLabels[r] = 1.0f;
    }
    for (int r = mA + mB + tid; r < NBOX; r += MNT) {
        reinterpret_cast<float4*>(outBoxes)[r] = make_float4(0.f, 0.f, 0.f, 0.f);
        outScores[r] = 0.0f;
        outLabels[r] = -1.0f;
    }
}

extern "C" void kernel_launch(void* const* d_in, const int* in_sizes, int n_in,
                              void* d_out, int out_size)
{
    const float* boxes  = (const float*)d_in[0];
    const float* scores = (const float*)d_in[1];
    const int*   labels = (const int*)d_in[2];
    float*       out    = (float*)d_out;

    size_t smem = sizeof(ScanSmem);
    cudaFuncSetAttribute(scan_kernel,
                         cudaFuncAttributeMaxDynamicSharedMemorySize, (int)smem);
    scan_kernel<<<2, NT, smem>>>(boxes, scores, labels);
    merge_kernel<<<1, MNT>>>(boxes, out);
}

// round 15
// speedup vs baseline: 3.3893x; 1.4532x over previous
#include <cuda_runtime.h>
#include <math.h>

#define NBOX 4096
#define NT   256                 // threads per class CTA (8 warps)
#define NW   (NT / 32)
#define EPT  9                   // contiguous slots per thread: 2304 capacity
#define RBEG (EPT * NT)
#define GC   8                   // 8x8 spatial grid, 128px cells
#define NCELL (GC * GC)
#define NCAND (NW * 4)
#define MAXB 32
#define FULL 0xFFFFFFFFu

typedef unsigned long long u64;
typedef unsigned u32;

__device__ u64 g_emit[2][NBOX];
__device__ int g_mcnt[2];

struct ScanSmem {
    float4 sbox[NBOX];           // orig-indexed boxes                64 KB
    float  cscore[NBOX];         // cell-sorted slot scores           16 KB
    int    corig[NBOX];          // slot -> orig index                16 KB
    u64    cand[NCAND];
    u32    cflag[NCAND];         // 1 = publication was lane's THIRD
    int    acc[MAXB];
    int    cstart[NCELL + 1];
    int    ccnt[NCELL];
    int    ccur[NCELL];
    int    cnt;
};

extern __shared__ char smem_raw[];

__device__ __forceinline__ u64 packkey(float s, int orig) {
    return ((u64)__float_as_uint(fmaxf(s, 0.0f)) << 32) | (u32)~orig;
}

__global__ __launch_bounds__(NT, 1)
void scan_kernel(const float* __restrict__ g_boxes,
                 const float* __restrict__ g_scores,
                 const int*   __restrict__ g_labels)
{
    ScanSmem* sm = reinterpret_cast<ScanSmem*>(smem_raw);
    const int cls = blockIdx.x;
    const int tid = threadIdx.x;
    const int wid = tid >> 5;
    const int lid = tid & 31;

    // ---- setup: load boxes; bin own class by 8x8 cell (spatial sort) ----
    for (int c = tid; c < NCELL; c += NT) { sm->ccnt[c] = 0; sm->ccur[c] = 0; }
    __syncthreads();
    for (int j = tid; j < NBOX; j += NT) {
        float4 b = reinterpret_cast<const float4*>(g_boxes)[j];
        sm->sbox[j] = b;
        if (g_labels[j] == cls) {
            int cell = ((((int)b.y) >> 7) << 3) | (((int)b.x) >> 7);
            atomicAdd(&sm->ccnt[cell], 1);
        }
    }
    __syncthreads();
    if (tid == 0) {
        int run = 0;
        for (int c = 0; c < NCELL; c++) { sm->cstart[c] = run; run += sm->ccnt[c]; }
        sm->cstart[NCELL] = run;
        sm->cnt = run;
    }
    __syncthreads();
    for (int j = tid; j < NBOX; j += NT) {
        if (g_labels[j] == cls) {
            float4 b = sm->sbox[j];
            int cell = ((((int)b.y) >> 7) << 3) | (((int)b.x) >> 7);
            int pos = sm->cstart[cell] + atomicAdd(&sm->ccur[cell], 1);
            sm->cscore[pos] = g_scores[j];
            sm->corig[pos]  = j;
        }
    }
    __syncthreads();
    const int Ng = sm->cnt;

    // ---- contiguous ownership: thread owns slots [tid*EPT, tid*EPT+EPT) ----
    float sc[EPT], bx[EPT], by[EPT], bz[EPT], bw[EPT], ar[EPT];
    int   org[EPT];
    float aax1 = 1e30f, aay1 = 1e30f, aax2 = -1e30f, aay2 = -1e30f;
#pragma unroll
    for (int k = 0; k < EPT; k++) {
        int s = tid * EPT + k;
        if (s < Ng) {
            int o = sm->corig[s];
            float4 b = sm->sbox[o];
            bx[k] = b.x; by[k] = b.y; bz[k] = b.z; bw[k] = b.w;
            ar[k] = (b.z - b.x) * (b.w - b.y);
            sc[k] = sm->cscore[s];
            org[k] = o;
            aax1 = fminf(aax1, b.x); aay1 = fminf(aay1, b.y);
            aax2 = fmaxf(aax2, b.z); aay2 = fmaxf(aay2, b.w);
        } else { sc[k] = -INFINITY; org[k] = -1; }
    }

    bool changed = true;
    u64  la0 = 0, la1 = 0, la2 = 0;   // cached local top-3 packed keys
    int  emitted = 0;

    while (true) {
        // ---- recompute local top-3 if owned set changed ----
        if (changed) {
            u64 a = 0, b = 0, c = 0;
#pragma unroll
            for (int k = 0; k < EPT; k++) {
                u64 v = (sc[k] == -INFINITY) ? 0ULL : packkey(sc[k], org[k]);
                if (v > a)      { c = b; b = a; a = v; }
                else if (v > b) { c = b; b = v; }
                else if (v > c) { c = v; }
            }
            for (int s = RBEG + tid; s < Ng; s += NT) {       // overflow (rare)
                float sv = sm->cscore[s];
                u64 v = (sv == -INFINITY) ? 0ULL : packkey(sv, sm->corig[s]);
                if (v > a)      { c = b; b = a; a = v; }
                else if (v > b) { c = b; b = v; }
                else if (v > c) { c = v; }
            }
            la0 = a; la1 = b; la2 = c;
            changed = false;
        }

        // ---- publish per-warp top-4 (lanes offer their top-3) ----
        {
            int p = 0;
#pragma unroll
            for (int r = 0; r < 4; r++) {
                u64 contrib = (p == 0) ? la0 : ((p == 1) ? la1 :
                              ((p == 2) ? la2 : 0ULL));
                u32 hi = (u32)(contrib >> 32);
                u32 wm = __reduce_max_sync(FULL, hi);
                u32 lo = (hi == wm) ? (u32)contrib : 0u;
                u32 wl = __reduce_max_sync(FULL, lo);
                u64 win = ((u64)wm << 32) | wl;
                if (win != 0ULL && contrib == win) {
                    sm->cand[wid * 4 + r]  = win;
                    sm->cflag[wid * 4 + r] = (p == 2) ? 1u : 0u;
                    p++;
                }
                if (win == 0ULL && lid == 0) sm->cand[wid * 4 + r] = 0ULL;
            }
        }
        __syncthreads();

        // ---- bound: >= every non-candidate's current key ----
        u64 ck = sm->cand[lid];
        u32 third = sm->cflag[lid];
        u64 bref = (ck != 0ULL && (third || (lid & 3) == 3)) ? ck : 0ULL;
        u32 bh = (u32)(bref >> 32);
        u32 bm = __reduce_max_sync(FULL, bh);
        u32 bl = (bh == bm) ? (u32)bref : 0u;
        u32 bml = __reduce_max_sync(FULL, bl);
        u64 bound = ((u64)bm << 32) | bml;

        int corig = -1; float csc = 0.0f, ca = 0.0f;
        float4 cb = make_float4(0.f, 0.f, 0.f, 0.f);
        if (ck != 0ULL) {
            corig = (int)~(u32)ck;
            csc = __uint_as_float((u32)(ck >> 32));
            cb = sm->sbox[corig];
            ca = (cb.z - cb.x) * (cb.w - cb.y);
        }
        u64 cur = ck;

        // ---- batch accept loop (no barriers) ----
        int bcount = 0;
        while (true) {
            u32 hi = (u32)(cur >> 32);
            u32 wm = __reduce_max_sync(FULL, hi);
            if (wm == 0u) break;
            u32 lo = (hi == wm) ? (u32)cur : 0u;
            u32 wl = __reduce_max_sync(FULL, lo);
            u64 win = ((u64)wm << 32) | wl;
            if (bcount > 0 && win < bound) break;
            int so = (int)~wl;
            if (tid == 0) { g_emit[cls][emitted] = win; sm->acc[bcount] = so; }
            emitted++; bcount++;

            float4 ab = sm->sbox[so];
            float  aa = (ab.z - ab.x) * (ab.w - ab.y);

            if (cur != 0ULL) {
                if (corig == so) cur = 0ULL;
                else {
                    float w = fminf(ab.z, cb.z) - fmaxf(ab.x, cb.x);
                    float h = fminf(ab.w, cb.w) - fmaxf(ab.y, cb.y);
                    if (w > 0.0f && h > 0.0f) {
                        float inter = w * h;
                        float iou = inter / ((aa + ca) - inter + 1e-8f);
                        float d   = expf(-(iou * iou) * 2.0f);
                        float nv  = csc * d;
                        if (nv >= 0.001f) {
                            csc = nv;
                            cur = ((u64)__float_as_uint(csc) << 32) | (u32)~corig;
                        } else cur = 0ULL;
                    }
                }
            }
            if (bcount >= MAXB) break;
        }

        if (bcount == 0) break;
        __syncthreads();

        // ---- deferred owned decay with AABB early-out (emission order) ----
        for (int b = 0; b < bcount; b++) {
            int so = sm->acc[b];
            float4 ab = sm->sbox[so];
            // Selected box inside owner's AABB -> owner always runs the loop.
            bool hit = (ab.x < aax2) && (ab.z > aax1) &&
                       (ab.y < aay2) && (ab.w > aay1);
            if (hit) {
                float aa = (ab.z - ab.x) * (ab.w - ab.y);
#pragma unroll
                for (int k = 0; k < EPT; k++) {
                    float v = sc[k];
                    if (v != -INFINITY) {
                        if (org[k] == so) { sc[k] = -INFINITY; changed = true; }
                        else {
                            float w = fminf(ab.z, bz[k]) - fmaxf(ab.x, bx[k]);
                            float h = fminf(ab.w, bw[k]) - fmaxf(ab.y, by[k]);
                            if (w > 0.0f && h > 0.0f) {
                                float inter = w * h;
                                float iou = inter / ((aa + ar[k]) - inter + 1e-8f);
                                float d   = expf(-(iou * iou) * 2.0f);
                                float nv  = v * d;
                                sc[k] = (nv >= 0.001f) ? nv : -INFINITY;
                                changed = true;
                            }
                        }
                    }
                }
            }
            for (int s = RBEG + tid; s < Ng; s += NT) {       // overflow (rare)
                float v = sm->cscore[s];
                if (v != -INFINITY) {
                    int o = sm->corig[s];
                    float aa = (ab.z - ab.x) * (ab.w - ab.y);
                    if (o == so) { sm->cscore[s] = -INFINITY; changed = true; }
                    else {
                        float4 b2 = sm->sbox[o];
                        float w = fminf(ab.z, b2.z) - fmaxf(ab.x, b2.x);
                        float h = fminf(ab.w, b2.w) - fmaxf(ab.y, b2.y);
                        if (w > 0.0f && h > 0.0f) {
                            float a2 = (b2.z - b2.x) * (b2.w - b2.y);
                            float inter = w * h;
                            float iou = inter / ((aa + a2) - inter + 1e-8f);
                            float d   = expf(-(iou * iou) * 2.0f);
                            float nv  = v * d;
                            sm->cscore[s] = (nv >= 0.001f) ? nv : -INFINITY;
                            changed = true;
                        }
                    }
                }
            }
        }
    }

    if (tid == 0) g_mcnt[cls] = emitted;
}

// ---------------- merge kernel (1 CTA, smem-staged keys) ----------------
#define MNT 1024
__global__ __launch_bounds__(MNT, 1)
void merge_kernel(const float* __restrict__ g_boxes,
                  float* __restrict__ g_out)
{
    __shared__ u64 sA[NBOX];
    const int tid = threadIdx.x;
    const int mA = g_mcnt[0];
    const int mB = g_mcnt[1];

    for (int i = tid; i < mA; i += MNT) sA[i]      = g_emit[0][i];
    for (int i = tid; i < mB; i += MNT) sA[mA + i] = g_emit[1][i];
    __syncthreads();

    float* outBoxes  = g_out;
    float* outScores = g_out + 4 * NBOX;
    float* outLabels = g_out + 5 * NBOX;

    for (int i = tid; i < mA; i += MNT) {
        u64 key = sA[i];
        int lo = 0, hi = mB;
        while (lo < hi) { int mid = (lo + hi) >> 1;
                          if (sA[mA + mid] > key) lo = mid + 1; else hi = mid; }
        int r = i + lo;
        int o = (int)~(u32)key;
        reinterpret_cast<float4*>(outBoxes)[r] =
            reinterpret_cast<const float4*>(g_boxes)[o];
        outScores[r] = __uint_as_float((u32)(key >> 32));
        outLabels[r] = 0.0f;
    }
    for (int i = tid; i < mB; i += MNT) {
        u64 key = sA[mA + i];
        int lo = 0, hi = mA;
        while (lo < hi) { int mid = (lo + hi) >> 1;
                          if (sA[mid] > key) lo = mid + 1; else hi = mid; }
        int r = i + lo;
        int o = (int)~(u32)key;
        reinterpret_cast<float4*>(outBoxes)[r] =
            reinterpret_cast<const float4*>(g_boxes)[o];
        outScores[r] = __uint_as_float((u32)(key >> 32));
        outLabels[r] = 1.0f;
    }
    for (int r = mA + mB + tid; r < NBOX; r += MNT) {
        reinterpret_cast<float4*>(outBoxes)[r] = make_float4(0.f, 0.f, 0.f, 0.f);
        outScores[r] = 0.0f;
        outLabels[r] = -1.0f;
    }
}

extern "C" void kernel_launch(void* const* d_in, const int* in_sizes, int n_in,
                              void* d_out, int out_size)
{
    const float* boxes  = (const float*)d_in[0];
    const float* scores = (const float*)d_in[1];
    const int*   labels = (const int*)d_in[2];
    float*       out    = (float*)d_out;

    size_t smem = sizeof(ScanSmem);
    cudaFuncSetAttribute(scan_kernel,
                         cudaFuncAttributeMaxDynamicSharedMemorySize, (int)smem);
    scan_kernel<<<2, NT, smem>>>(boxes, scores, labels);
    merge_kernel<<<1, MNT>>>(boxes, out);
}